// round 1
// baseline (speedup 1.0000x reference)
#include <cuda_runtime.h>
#include <cuda_fp16.h>
#include <mma.h>

using namespace nvcuda;

#define N_NODES 100000
#define N_EDGES 640000
#define WID     128
#define NFEAT   64
#define KE      192      // WID + NFEAT
#define KM      256      // 2*WID

// smem layouts (halves padded to kill bank conflicts; ldm multiples of 8)
#define A_LD_E  200      // 128 x 200 halves
#define B_LD    136      // K x 136 halves
#define C_LD    132      // 128 x 132 floats
#define A_LD_N  264      // 128 x 264 halves

#define SMEM_EDGE (128*A_LD_E*2 + KE*B_LD*2 + 128*C_LD*4)   // 51200+52224+67584 = 171008
#define SMEM_NODE (128*A_LD_N*2 + KM*B_LD*2 + 128*C_LD*4)   // 67584+69632+67584 = 204800

#define ENC_NEG_INF 0x007FFFFFu   // enc(-inf)

// ---------- scratch (device globals; no cudaMalloc allowed) ----------
__device__ unsigned g_maxes[(size_t)N_NODES * WID];   // 51.2 MB, order-encoded f32
__device__ __half   g_We[KE * WID];
__device__ __half   g_Wm[KM * WID];

// order-preserving float -> u32 encoding (atomicMax-able)
__device__ __forceinline__ unsigned enc_f(float f) {
    unsigned u = __float_as_uint(f);
    return (u & 0x80000000u) ? ~u : (u | 0x80000000u);
}
__device__ __forceinline__ float dec_or_zero(unsigned v) {
    if (v == ENC_NEG_INF) return 0.0f;                 // empty segment -> 0
    unsigned u = (v & 0x80000000u) ? (v ^ 0x80000000u) : ~v;
    return __uint_as_float(u);
}

// ---------- kernel 0: convert weights to fp16, reset segment-max buffer ----------
__global__ void prep_kernel(const float* __restrict__ We, const float* __restrict__ Wm) {
    int i = blockIdx.x * blockDim.x + threadIdx.x;
    if (i < KE * WID) g_We[i] = __float2half_rn(We[i]);
    if (i < KM * WID) g_Wm[i] = __float2half_rn(Wm[i]);
    if (i < N_NODES * WID) g_maxes[i] = ENC_NEG_INF;
}

// ---------- kernel 1: fused edge MLP + segment-max(atomic) ----------
// block = 256 threads, tile = 128 edges x 128 out, K=192
__global__ __launch_bounds__(256, 1)
void edge_kernel(const float* __restrict__ x, const int* __restrict__ e,
                 const float* __restrict__ efeat, const float* __restrict__ b_edge) {
    extern __shared__ __align__(16) char smem[];
    __half* sA = (__half*)smem;                                   // [128][A_LD_E]
    __half* sB = (__half*)(smem + 128 * A_LD_E * 2);              // [KE][B_LD]
    float*  sC = (float*)(smem + 128 * A_LD_E * 2 + KE * B_LD * 2); // [128][C_LD]
    __shared__ int s_dst[128];

    const int tid  = threadIdx.x;
    const int lane = tid & 31;
    const int wid  = tid >> 5;           // 0..7
    const int ebase = blockIdx.x * 128;

    // stage W_edge (fp16) : KE*WID halves = KE*16 uint4
    {
        const uint4* gB = (const uint4*)g_We;
        for (int i = tid; i < KE * 16; i += 256) {
            int k = i >> 4, c = i & 15;
            *((uint4*)(sB + k * B_LD) + c) = gB[i];
        }
    }

    // stage A: rows = edges; cols 0..127 = x[dst]-x[src] (fp16), 128..191 = e_feat
    const float4* x4 = (const float4*)x;
    const float4* f4 = (const float4*)efeat;
    #pragma unroll 4
    for (int it = 0; it < 16; ++it) {
        int r = wid * 16 + it;
        int eidx = ebase + r;
        int src = e[eidx];
        int dst = e[N_EDGES + eidx];
        float4 a = x4[(size_t)dst * 32 + lane];
        float4 b = x4[(size_t)src * 32 + lane];
        __half2* arow = (__half2*)(sA + r * A_LD_E);
        arow[lane * 2 + 0] = __floats2half2_rn(a.x - b.x, a.y - b.y);
        arow[lane * 2 + 1] = __floats2half2_rn(a.z - b.z, a.w - b.w);
        if (lane < 16) {
            float4 f = f4[(size_t)eidx * 16 + lane];
            __half2* frow = (__half2*)(sA + r * A_LD_E + 128);
            frow[lane * 2 + 0] = __floats2half2_rn(f.x, f.y);
            frow[lane * 2 + 1] = __floats2half2_rn(f.z, f.w);
        }
        if (lane == 0) s_dst[r] = dst;
    }
    __syncthreads();

    // GEMM: warp (wm, wn) computes 32x64 region. wm=wid&3, wn=wid>>2
    {
        const int wm = wid & 3, wn = wid >> 2;
        wmma::fragment<wmma::accumulator, 16, 16, 16, float> c[2][4];
        #pragma unroll
        for (int i = 0; i < 2; i++)
            #pragma unroll
            for (int j = 0; j < 4; j++) wmma::fill_fragment(c[i][j], 0.0f);

        #pragma unroll
        for (int k = 0; k < KE / 16; ++k) {
            wmma::fragment<wmma::matrix_a, 16, 16, 16, __half, wmma::row_major> a[2];
            wmma::load_matrix_sync(a[0], sA + (wm * 32 +  0) * A_LD_E + k * 16, A_LD_E);
            wmma::load_matrix_sync(a[1], sA + (wm * 32 + 16) * A_LD_E + k * 16, A_LD_E);
            #pragma unroll
            for (int j = 0; j < 4; j++) {
                wmma::fragment<wmma::matrix_b, 16, 16, 16, __half, wmma::row_major> b;
                wmma::load_matrix_sync(b, sB + (k * 16) * B_LD + wn * 64 + j * 16, B_LD);
                wmma::mma_sync(c[0][j], a[0], b, c[0][j]);
                wmma::mma_sync(c[1][j], a[1], b, c[1][j]);
            }
        }
        #pragma unroll
        for (int i = 0; i < 2; i++)
            #pragma unroll
            for (int j = 0; j < 4; j++)
                wmma::store_matrix_sync(sC + (wm * 32 + i * 16) * C_LD + wn * 64 + j * 16,
                                        c[i][j], C_LD, wmma::mem_row_major);
    }
    __syncthreads();

    // epilogue: ef = diffs + relu(C + b); segment-max via encoded RED.max.u32
    {
        float4 bv = ((const float4*)b_edge)[lane];
        #pragma unroll 4
        for (int it = 0; it < 16; ++it) {
            int m = wid * 16 + it;
            unsigned base = (unsigned)s_dst[m] * (unsigned)WID + lane * 4;
            const float*  crow = sC + m * C_LD + lane * 4;
            const __half* arow = sA + m * A_LD_E + lane * 4;
            float v0 = fmaxf(crow[0] + bv.x, 0.0f) + __half2float(arow[0]);
            float v1 = fmaxf(crow[1] + bv.y, 0.0f) + __half2float(arow[1]);
            float v2 = fmaxf(crow[2] + bv.z, 0.0f) + __half2float(arow[2]);
            float v3 = fmaxf(crow[3] + bv.w, 0.0f) + __half2float(arow[3]);
            atomicMax(&g_maxes[base + 0], enc_f(v0));
            atomicMax(&g_maxes[base + 1], enc_f(v1));
            atomicMax(&g_maxes[base + 2], enc_f(v2));
            atomicMax(&g_maxes[base + 3], enc_f(v3));
        }
    }
}

// ---------- kernel 2: node MLP + residual ----------
// block = 256 threads, tile = 128 nodes x 128 out, K=256
__global__ __launch_bounds__(256, 1)
void node_kernel(const float* __restrict__ x, const float* __restrict__ b_mlp,
                 float* __restrict__ out) {
    extern __shared__ __align__(16) char smem[];
    __half* sA = (__half*)smem;                                    // [128][A_LD_N]
    __half* sB = (__half*)(smem + 128 * A_LD_N * 2);               // [KM][B_LD]
    float*  sC = (float*)(smem + 128 * A_LD_N * 2 + KM * B_LD * 2);  // [128][C_LD]

    const int tid  = threadIdx.x;
    const int lane = tid & 31;
    const int wid  = tid >> 5;
    const int nbase = blockIdx.x * 128;

    // stage W_mlp
    {
        const uint4* gB = (const uint4*)g_Wm;
        for (int i = tid; i < KM * 16; i += 256) {
            int k = i >> 4, c = i & 15;
            *((uint4*)(sB + k * B_LD) + c) = gB[i];
        }
    }

    // stage A: cols 0..127 = x (fp16), 128..255 = decoded segment maxes
    const float4* x4 = (const float4*)x;
    #pragma unroll 4
    for (int it = 0; it < 16; ++it) {
        int r = wid * 16 + it;
        int node = nbase + r;
        __half2* arow = (__half2*)(sA + r * A_LD_N);
        __half2* mrow = (__half2*)(sA + r * A_LD_N + 128);
        if (node < N_NODES) {
            float4 a = x4[(size_t)node * 32 + lane];
            arow[lane * 2 + 0] = __floats2half2_rn(a.x, a.y);
            arow[lane * 2 + 1] = __floats2half2_rn(a.z, a.w);
            uint4 mv = ((const uint4*)g_maxes)[(size_t)node * 32 + lane];
            mrow[lane * 2 + 0] = __floats2half2_rn(dec_or_zero(mv.x), dec_or_zero(mv.y));
            mrow[lane * 2 + 1] = __floats2half2_rn(dec_or_zero(mv.z), dec_or_zero(mv.w));
        } else {
            __half2 z = __floats2half2_rn(0.0f, 0.0f);
            arow[lane * 2 + 0] = z; arow[lane * 2 + 1] = z;
            mrow[lane * 2 + 0] = z; mrow[lane * 2 + 1] = z;
        }
    }
    __syncthreads();

    // GEMM K=256
    {
        const int wm = wid & 3, wn = wid >> 2;
        wmma::fragment<wmma::accumulator, 16, 16, 16, float> c[2][4];
        #pragma unroll
        for (int i = 0; i < 2; i++)
            #pragma unroll
            for (int j = 0; j < 4; j++) wmma::fill_fragment(c[i][j], 0.0f);

        #pragma unroll
        for (int k = 0; k < KM / 16; ++k) {
            wmma::fragment<wmma::matrix_a, 16, 16, 16, __half, wmma::row_major> a[2];
            wmma::load_matrix_sync(a[0], sA + (wm * 32 +  0) * A_LD_N + k * 16, A_LD_N);
            wmma::load_matrix_sync(a[1], sA + (wm * 32 + 16) * A_LD_N + k * 16, A_LD_N);
            #pragma unroll
            for (int j = 0; j < 4; j++) {
                wmma::fragment<wmma::matrix_b, 16, 16, 16, __half, wmma::row_major> b;
                wmma::load_matrix_sync(b, sB + (k * 16) * B_LD + wn * 64 + j * 16, B_LD);
                wmma::mma_sync(c[0][j], a[0], b, c[0][j]);
                wmma::mma_sync(c[1][j], a[1], b, c[1][j]);
            }
        }
        #pragma unroll
        for (int i = 0; i < 2; i++)
            #pragma unroll
            for (int j = 0; j < 4; j++)
                wmma::store_matrix_sync(sC + (wm * 32 + i * 16) * C_LD + wn * 64 + j * 16,
                                        c[i][j], C_LD, wmma::mem_row_major);
    }
    __syncthreads();

    // epilogue: out = x + relu(C + b_mlp)   (x re-read in fp32; coalesced)
    {
        float4 bv = ((const float4*)b_mlp)[lane];
        #pragma unroll 4
        for (int it = 0; it < 16; ++it) {
            int m = wid * 16 + it;
            int node = nbase + m;
            if (node >= N_NODES) continue;
            const float* crow = sC + m * C_LD + lane * 4;
            float4 xv = ((const float4*)x)[(size_t)node * 32 + lane];
            float4 o;
            o.x = xv.x + fmaxf(crow[0] + bv.x, 0.0f);
            o.y = xv.y + fmaxf(crow[1] + bv.y, 0.0f);
            o.z = xv.z + fmaxf(crow[2] + bv.z, 0.0f);
            o.w = xv.w + fmaxf(crow[3] + bv.w, 0.0f);
            ((float4*)out)[(size_t)node * 32 + lane] = o;
        }
    }
}

extern "C" void kernel_launch(void* const* d_in, const int* in_sizes, int n_in,
                              void* d_out, int out_size) {
    const float* x     = (const float*)d_in[0];
    const int*   e     = (const int*)d_in[1];
    const float* efeat = (const float*)d_in[2];
    const float* We    = (const float*)d_in[3];
    const float* be    = (const float*)d_in[4];
    const float* Wm    = (const float*)d_in[5];
    const float* bm    = (const float*)d_in[6];
    float* out = (float*)d_out;

    cudaFuncSetAttribute(edge_kernel, cudaFuncAttributeMaxDynamicSharedMemorySize, SMEM_EDGE);
    cudaFuncSetAttribute(node_kernel, cudaFuncAttributeMaxDynamicSharedMemorySize, SMEM_NODE);

    prep_kernel<<<(N_NODES * WID + 255) / 256, 256>>>(We, Wm);
    edge_kernel<<<N_EDGES / 128, 256, SMEM_EDGE>>>(x, e, efeat, be);
    node_kernel<<<(N_NODES + 127) / 128, 256, SMEM_NODE>>>(x, bm, out);
}

// round 3
// speedup vs baseline: 1.7831x; 1.7831x over previous
#include <cuda_runtime.h>
#include <cuda_fp16.h>
#include <mma.h>

using namespace nvcuda;

#define N_NODES 100000
#define N_EDGES 640000
#define WID     128
#define NFEAT   64
#define KE      192      // WID + NFEAT
#define KM      256      // 2*WID

// ---- edge kernel smem layout (bytes) ----
#define A1_LD 136
#define A2_LD 72
#define B_LD  136
#define C_LD  132
#define SDIFF_BYTES (128*A1_LD*2)
#define SFEAT_BYTES (128*A2_LD*2)
#define SB_E_BYTES  (KE*B_LD*2)
#define SMEM_EDGE   (SDIFF_BYTES + SFEAT_BYTES + SB_E_BYTES)   // 105472 -> 2 blocks/SM

// ---- node kernel smem ----
#define A_LD_N  264
#define SMEM_NODE (128*A_LD_N*2 + KM*B_LD*2 + 128*C_LD*4)      // 204800

#define HNEG_INF2 0xFC00FC00u   // packed f16x2 (-inf, -inf)

// ---------- scratch (device globals) ----------
__device__ unsigned g_maxes[(size_t)N_NODES * (WID/2)];   // 25.6 MB, f16x2 per word
__device__ __half   g_We[KE * WID];
__device__ __half   g_Wm[KM * WID];

// vector-form packed-half reduction (ptxas on sm_103 requires .v2.f16 spelling)
__device__ __forceinline__ void red_max_h2(unsigned* addr, unsigned val) {
    unsigned short lo = (unsigned short)(val & 0xFFFFu);
    unsigned short hi = (unsigned short)(val >> 16);
    asm volatile("red.global.v2.f16.max.noftz [%0], {%1, %2};"
                 :: "l"(addr), "h"(lo), "h"(hi) : "memory");
}
// replace any -inf f16 half with +0
__device__ __forceinline__ unsigned fix_neginf(unsigned v) {
    if ((v & 0xFFFFu) == 0xFC00u) v &= 0xFFFF0000u;
    if ((v >> 16)     == 0xFC00u) v &= 0x0000FFFFu;
    return v;
}

// ---------- kernel 0: weights -> fp16, reset segment-max buffer ----------
__global__ void prep_kernel(const float* __restrict__ We, const float* __restrict__ Wm) {
    int i = blockIdx.x * blockDim.x + threadIdx.x;
    if (i < KE * WID) g_We[i] = __float2half_rn(We[i]);
    if (i < KM * WID) g_Wm[i] = __float2half_rn(Wm[i]);
    if (i < N_NODES * (WID/2)) g_maxes[i] = HNEG_INF2;
}

// ---------- kernel 1: fused edge MLP + segment-max ----------
// block = 256 threads, tile = 128 edges x 128 out, K = 192
__global__ __launch_bounds__(256, 2)
void edge_kernel(const float* __restrict__ x, const int* __restrict__ e,
                 const float* __restrict__ efeat, const float* __restrict__ b_edge) {
    extern __shared__ __align__(16) char smem[];
    __half* sDiff = (__half*)smem;                                // [128][A1_LD]
    __half* sFeat = (__half*)(smem + SDIFF_BYTES);                // [128][A2_LD]
    __half* sB    = (__half*)(smem + SDIFF_BYTES + SFEAT_BYTES);  // [KE][B_LD]
    float*  sC    = (float*)(smem + SDIFF_BYTES);                 // overlay [128][C_LD]
    __shared__ int s_dst[128];

    const int tid  = threadIdx.x;
    const int lane = tid & 31;
    const int wid  = tid >> 5;           // 0..7
    const int ebase = blockIdx.x * 128;

    // stage W_edge (fp16): KE*WID halves = KE*16 uint4
    {
        const uint4* gB = (const uint4*)g_We;
        for (int i = tid; i < KE * 16; i += 256) {
            int k = i >> 4, c = i & 15;
            *((uint4*)(sB + k * B_LD) + c) = gB[i];
        }
    }

    // stage A: sDiff = fp16(x[dst]-x[src]); sFeat = fp16(e_feat)
    const float4* x4 = (const float4*)x;
    const float4* f4 = (const float4*)efeat;
    #pragma unroll 4
    for (int it = 0; it < 16; ++it) {
        int r = wid * 16 + it;
        int eidx = ebase + r;
        int src = e[eidx];
        int dst = e[N_EDGES + eidx];
        float4 a = x4[(size_t)dst * 32 + lane];
        float4 b = x4[(size_t)src * 32 + lane];
        __half2* drow = (__half2*)(sDiff + r * A1_LD);
        drow[lane * 2 + 0] = __floats2half2_rn(a.x - b.x, a.y - b.y);
        drow[lane * 2 + 1] = __floats2half2_rn(a.z - b.z, a.w - b.w);
        if (lane < 16) {
            float4 f = f4[(size_t)eidx * 16 + lane];
            __half2* frow = (__half2*)(sFeat + r * A2_LD);
            frow[lane * 2 + 0] = __floats2half2_rn(f.x, f.y);
            frow[lane * 2 + 1] = __floats2half2_rn(f.z, f.w);
        }
        if (lane == 0) s_dst[r] = dst;
    }
    __syncthreads();

    // GEMM: warp (wm, wn) computes 32x64 region; K split: diffs (8 steps) + feat (4 steps)
    const int wm = wid & 3, wn = wid >> 2;
    wmma::fragment<wmma::accumulator, 16, 16, 16, float> c[2][4];
    #pragma unroll
    for (int i = 0; i < 2; i++)
        #pragma unroll
        for (int j = 0; j < 4; j++) wmma::fill_fragment(c[i][j], 0.0f);

    #pragma unroll
    for (int k = 0; k < 12; ++k) {
        wmma::fragment<wmma::matrix_a, 16, 16, 16, __half, wmma::row_major> a[2];
        if (k < 8) {
            wmma::load_matrix_sync(a[0], sDiff + (wm * 32 +  0) * A1_LD + k * 16, A1_LD);
            wmma::load_matrix_sync(a[1], sDiff + (wm * 32 + 16) * A1_LD + k * 16, A1_LD);
        } else {
            wmma::load_matrix_sync(a[0], sFeat + (wm * 32 +  0) * A2_LD + (k - 8) * 16, A2_LD);
            wmma::load_matrix_sync(a[1], sFeat + (wm * 32 + 16) * A2_LD + (k - 8) * 16, A2_LD);
        }
        #pragma unroll
        for (int j = 0; j < 4; j++) {
            wmma::fragment<wmma::matrix_b, 16, 16, 16, __half, wmma::row_major> b;
            wmma::load_matrix_sync(b, sB + (k * 16) * B_LD + wn * 64 + j * 16, B_LD);
            wmma::mma_sync(c[0][j], a[0], b, c[0][j]);
            wmma::mma_sync(c[1][j], a[1], b, c[1][j]);
        }
    }
    __syncthreads();   // everyone done reading sFeat/sB before C overlays them

    #pragma unroll
    for (int i = 0; i < 2; i++)
        #pragma unroll
        for (int j = 0; j < 4; j++)
            wmma::store_matrix_sync(sC + (wm * 32 + i * 16) * C_LD + wn * 64 + j * 16,
                                    c[i][j], C_LD, wmma::mem_row_major);
    __syncthreads();

    // epilogue: ef = diffs + relu(C + b); segment-max via red.v2.f16.max
    {
        float4 bv = ((const float4*)b_edge)[lane];
        #pragma unroll 4
        for (int it = 0; it < 16; ++it) {
            int m = wid * 16 + it;
            unsigned base = (unsigned)s_dst[m] * (unsigned)(WID/2) + lane * 2;
            const float*  crow = sC    + m * C_LD  + lane * 4;
            const __half* drow = sDiff + m * A1_LD + lane * 4;
            float v0 = fmaxf(crow[0] + bv.x, 0.0f) + __half2float(drow[0]);
            float v1 = fmaxf(crow[1] + bv.y, 0.0f) + __half2float(drow[1]);
            float v2 = fmaxf(crow[2] + bv.z, 0.0f) + __half2float(drow[2]);
            float v3 = fmaxf(crow[3] + bv.w, 0.0f) + __half2float(drow[3]);
            __half2 p0 = __floats2half2_rn(v0, v1);
            __half2 p1 = __floats2half2_rn(v2, v3);
            red_max_h2(&g_maxes[base + 0], *(unsigned*)&p0);
            red_max_h2(&g_maxes[base + 1], *(unsigned*)&p1);
        }
    }
}

// ---------- kernel 2: node MLP + residual ----------
__global__ __launch_bounds__(256, 1)
void node_kernel(const float* __restrict__ x, const float* __restrict__ b_mlp,
                 float* __restrict__ out) {
    extern __shared__ __align__(16) char smem[];
    __half* sA = (__half*)smem;                                    // [128][A_LD_N]
    __half* sB = (__half*)(smem + 128 * A_LD_N * 2);               // [KM][B_LD]
    float*  sC = (float*)(smem + 128 * A_LD_N * 2 + KM * B_LD * 2);  // [128][C_LD]

    const int tid  = threadIdx.x;
    const int lane = tid & 31;
    const int wid  = tid >> 5;
    const int nbase = blockIdx.x * 128;

    // stage W_mlp
    {
        const uint4* gB = (const uint4*)g_Wm;
        for (int i = tid; i < KM * 16; i += 256) {
            int k = i >> 4, c = i & 15;
            *((uint4*)(sB + k * B_LD) + c) = gB[i];
        }
    }

    // stage A: cols 0..127 = fp16(x), 128..255 = maxes (already fp16)
    const float4* x4 = (const float4*)x;
    #pragma unroll 4
    for (int it = 0; it < 16; ++it) {
        int r = wid * 16 + it;
        int node = nbase + r;
        __half2* arow = (__half2*)(sA + r * A_LD_N);
        __half2* mrow = (__half2*)(sA + r * A_LD_N + 128);
        if (node < N_NODES) {
            float4 a = x4[(size_t)node * 32 + lane];
            arow[lane * 2 + 0] = __floats2half2_rn(a.x, a.y);
            arow[lane * 2 + 1] = __floats2half2_rn(a.z, a.w);
            uint2 mv = ((const uint2*)g_maxes)[(size_t)node * 32 + lane];
            unsigned m0 = fix_neginf(mv.x);
            unsigned m1 = fix_neginf(mv.y);
            mrow[lane * 2 + 0] = *(__half2*)&m0;
            mrow[lane * 2 + 1] = *(__half2*)&m1;
        } else {
            __half2 z = __floats2half2_rn(0.0f, 0.0f);
            arow[lane * 2 + 0] = z; arow[lane * 2 + 1] = z;
            mrow[lane * 2 + 0] = z; mrow[lane * 2 + 1] = z;
        }
    }
    __syncthreads();

    // GEMM K=256
    {
        const int wm = wid & 3, wn = wid >> 2;
        wmma::fragment<wmma::accumulator, 16, 16, 16, float> c[2][4];
        #pragma unroll
        for (int i = 0; i < 2; i++)
            #pragma unroll
            for (int j = 0; j < 4; j++) wmma::fill_fragment(c[i][j], 0.0f);

        #pragma unroll
        for (int k = 0; k < KM / 16; ++k) {
            wmma::fragment<wmma::matrix_a, 16, 16, 16, __half, wmma::row_major> a[2];
            wmma::load_matrix_sync(a[0], sA + (wm * 32 +  0) * A_LD_N + k * 16, A_LD_N);
            wmma::load_matrix_sync(a[1], sA + (wm * 32 + 16) * A_LD_N + k * 16, A_LD_N);
            #pragma unroll
            for (int j = 0; j < 4; j++) {
                wmma::fragment<wmma::matrix_b, 16, 16, 16, __half, wmma::row_major> b;
                wmma::load_matrix_sync(b, sB + (k * 16) * B_LD + wn * 64 + j * 16, B_LD);
                wmma::mma_sync(c[0][j], a[0], b, c[0][j]);
                wmma::mma_sync(c[1][j], a[1], b, c[1][j]);
            }
        }
        #pragma unroll
        for (int i = 0; i < 2; i++)
            #pragma unroll
            for (int j = 0; j < 4; j++)
                wmma::store_matrix_sync(sC + (wm * 32 + i * 16) * C_LD + wn * 64 + j * 16,
                                        c[i][j], C_LD, wmma::mem_row_major);
    }
    __syncthreads();

    // epilogue: out = x + relu(C + b_mlp)
    {
        float4 bv = ((const float4*)b_mlp)[lane];
        #pragma unroll 4
        for (int it = 0; it < 16; ++it) {
            int m = wid * 16 + it;
            int node = nbase + m;
            if (node >= N_NODES) continue;
            const float* crow = sC + m * C_LD + lane * 4;
            float4 xv = ((const float4*)x)[(size_t)node * 32 + lane];
            float4 o;
            o.x = xv.x + fmaxf(crow[0] + bv.x, 0.0f);
            o.y = xv.y + fmaxf(crow[1] + bv.y, 0.0f);
            o.z = xv.z + fmaxf(crow[2] + bv.z, 0.0f);
            o.w = xv.w + fmaxf(crow[3] + bv.w, 0.0f);
            ((float4*)out)[(size_t)node * 32 + lane] = o;
        }
    }
}

extern "C" void kernel_launch(void* const* d_in, const int* in_sizes, int n_in,
                              void* d_out, int out_size) {
    const float* x     = (const float*)d_in[0];
    const int*   e     = (const int*)d_in[1];
    const float* efeat = (const float*)d_in[2];
    const float* We    = (const float*)d_in[3];
    const float* be    = (const float*)d_in[4];
    const float* Wm    = (const float*)d_in[5];
    const float* bm    = (const float*)d_in[6];
    float* out = (float*)d_out;

    cudaFuncSetAttribute(edge_kernel, cudaFuncAttributeMaxDynamicSharedMemorySize, SMEM_EDGE);
    cudaFuncSetAttribute(node_kernel, cudaFuncAttributeMaxDynamicSharedMemorySize, SMEM_NODE);

    prep_kernel<<<(N_NODES * (WID/2) + 255) / 256, 256>>>(We, Wm);
    edge_kernel<<<N_EDGES / 128, 256, SMEM_EDGE>>>(x, e, efeat, be);
    node_kernel<<<(N_NODES + 127) / 128, 256, SMEM_NODE>>>(x, bm, out);
}